// round 1
// baseline (speedup 1.0000x reference)
#include <cuda_runtime.h>

// ============================================================================
// out[b,o] = logsumexp_k( x[b,k] + log_softmax(w)[o,k] )
//          = log( sum_k e^x[b,k] * e^w[o,k] ) - log( sum_k e^w[o,k] )
// Linear-domain split-K SGEMM (M=N=128, K=16384) + row-sum + log epilogue.
// ============================================================================

#define B_DIM   128
#define O_DIM   128
#define K_DIM   16384
#define NSPLIT  128          // split-K blocks
#define KCHUNK  (K_DIM / NSPLIT)   // 128 K per block
#define KSUB    32           // K per smem stage
#define PAD     132          // padded row stride (words) for transposed tiles

// Scratch (static device globals — no runtime allocation)
__device__ float g_part[NSPLIT * B_DIM * O_DIM];   // 8 MB split-K partials
__device__ float g_rpart[NSPLIT * O_DIM];          // partial row sums of e^w

__global__ __launch_bounds__(256, 1)
void srl_gemm_kernel(const float* __restrict__ x, const float* __restrict__ w) {
    __shared__ float xs[KSUB * PAD];   // xs[kk][b]  (transposed)
    __shared__ float ws[KSUB * PAD];   // ws[kk][o]  (transposed)

    const int tid = threadIdx.x;
    const int tx  = tid & 15;          // -> o tile
    const int ty  = tid >> 4;          // -> b tile
    const int kbase = blockIdx.x * KCHUNK;

    float acc[8][8];
#pragma unroll
    for (int i = 0; i < 8; i++)
#pragma unroll
        for (int j = 0; j < 8; j++) acc[i][j] = 0.f;

    float rsum = 0.f;

    for (int sub = 0; sub < KCHUNK / KSUB; sub++) {
        const int k0 = kbase + sub * KSUB;

        // Load 128x32 of x and w, exp(), store transposed into smem.
        // Warp reads one contiguous 128B row segment -> fully coalesced.
#pragma unroll
        for (int it = 0; it < (B_DIM * KSUB) / 256; it++) {   // 16 iters
            int idx = it * 256 + tid;
            int row = idx >> 5;        // 0..127
            int kk  = idx & 31;        // 0..31
            xs[kk * PAD + row] = __expf(x[row * K_DIM + k0 + kk]);
            ws[kk * PAD + row] = __expf(w[row * K_DIM + k0 + kk]);
        }
        __syncthreads();

        // Partial row sums of e^w (threads 0..127, conflict-free stride-1 LDS)
        if (tid < O_DIM) {
#pragma unroll
            for (int kk = 0; kk < KSUB; kk++) rsum += ws[kk * PAD + tid];
        }

        // 8x8 register microtile GEMM over this K slab
#pragma unroll 4
        for (int kk = 0; kk < KSUB; kk++) {
            float4 a0 = *(const float4*)&xs[kk * PAD + ty * 4];
            float4 a1 = *(const float4*)&xs[kk * PAD + 64 + ty * 4];
            float4 b0 = *(const float4*)&ws[kk * PAD + tx * 4];
            float4 b1 = *(const float4*)&ws[kk * PAD + 64 + tx * 4];
            float a[8] = {a0.x, a0.y, a0.z, a0.w, a1.x, a1.y, a1.z, a1.w};
            float b[8] = {b0.x, b0.y, b0.z, b0.w, b1.x, b1.y, b1.z, b1.w};
#pragma unroll
            for (int i = 0; i < 8; i++)
#pragma unroll
                for (int j = 0; j < 8; j++)
                    acc[i][j] = fmaf(a[i], b[j], acc[i][j]);
        }
        __syncthreads();
    }

    if (tid < O_DIM) g_rpart[blockIdx.x * O_DIM + tid] = rsum;

    // Store the 128x128 partial tile (vectorized, coalesced across tx)
    float* dst = &g_part[blockIdx.x * (B_DIM * O_DIM)];
#pragma unroll
    for (int i = 0; i < 8; i++) {
        int b = (i < 4) ? (ty * 4 + i) : (64 + ty * 4 + (i - 4));
        *(float4*)&dst[b * O_DIM + tx * 4] =
            make_float4(acc[i][0], acc[i][1], acc[i][2], acc[i][3]);
        *(float4*)&dst[b * O_DIM + 64 + tx * 4] =
            make_float4(acc[i][4], acc[i][5], acc[i][6], acc[i][7]);
    }
}

__global__ __launch_bounds__(128)
void srl_finalize_kernel(float* __restrict__ out) {
    const int b = blockIdx.x;
    const int o = threadIdx.x;
    float s = 0.f, r = 0.f;
#pragma unroll 8
    for (int sp = 0; sp < NSPLIT; sp++) {
        s += g_part[sp * (B_DIM * O_DIM) + b * O_DIM + o];
        r += g_rpart[sp * O_DIM + o];
    }
    out[b * O_DIM + o] = __logf(s) - __logf(r);
}

extern "C" void kernel_launch(void* const* d_in, const int* in_sizes, int n_in,
                              void* d_out, int out_size) {
    (void)in_sizes; (void)n_in; (void)out_size;
    const float* x = (const float*)d_in[0];   // [128, 16*32*32] = [128, 16384]
    const float* w = (const float*)d_in[1];   // [128, 16384]
    float* out = (float*)d_out;               // [128, 128]

    srl_gemm_kernel<<<NSPLIT, 256>>>(x, w);
    srl_finalize_kernel<<<B_DIM, O_DIM>>>(out);
}

// round 2
// speedup vs baseline: 2.0112x; 2.0112x over previous
#include <cuda_runtime.h>
#include <cuda_bf16.h>
#include <cstdint>

// ============================================================================
// out[b,o] = logsumexp_k( x[b,k] + log_softmax(w)[o,k] )
//          = log( sum_k e^x * e^w ) - log( sum_k e^w )
// Linear domain, split-K, bf16 tensor-core GEMM (M=N=128, K=16384).
// ============================================================================

#define B_DIM  128
#define O_DIM  128
#define K_DIM  16384
#define NSPLIT 128
#define KCHUNK 128            // K per block
#define NSUB   4              // pipeline stages per block
#define KSUB   32             // K per stage
#define LDSR   40             // smem row stride in bf16 (80B: 16B-aligned, conflict-free ldmatrix)

__device__ float g_part[NSPLIT * B_DIM * O_DIM];   // split-K partials (8 MB)
__device__ float g_rpart[NSPLIT * O_DIM];          // partial row sums of e^w

__device__ __forceinline__ uint32_t smem_u32(const void* p) {
    return (uint32_t)__cvta_generic_to_shared(p);
}

__global__ __launch_bounds__(256, 1)
void srl_gemm_kernel(const float* __restrict__ x, const float* __restrict__ w) {
    __shared__ __align__(16) __nv_bfloat16 sA[2][B_DIM * LDSR];
    __shared__ __align__(16) __nv_bfloat16 sB[2][B_DIM * LDSR];

    const int tid  = threadIdx.x;
    const int lane = tid & 31;
    const int wid  = tid >> 5;
    const int kbase = blockIdx.x * KCHUNK;

    // Load assignment: 2 threads per row, each owns 64 contiguous bytes/stage.
    const int lrow  = tid >> 1;
    const int khalf = tid & 1;
    const float4* xp4 = (const float4*)(x + (size_t)lrow * K_DIM + kbase);
    const float4* wp4 = (const float4*)(w + (size_t)lrow * K_DIM + kbase);

    // Warp tile: 2 (m) x 4 (n) warps, each 64x32 of the 128x128 output.
    const int m0 = (wid >> 2) * 64;
    const int n0 = (wid & 3) * 32;

    float acc[4][4][4];
#pragma unroll
    for (int mi = 0; mi < 4; mi++)
#pragma unroll
        for (int nj = 0; nj < 4; nj++)
#pragma unroll
            for (int q = 0; q < 4; q++) acc[mi][nj][q] = 0.f;

    float4 rx[4], rw[4];
#pragma unroll
    for (int j = 0; j < 4; j++) {             // preload stage 0
        rx[j] = xp4[khalf * 4 + j];
        rw[j] = wp4[khalf * 4 + j];
    }

    float rsum = 0.f;

    for (int sub = 0; sub < NSUB; ++sub) {
        const int buf = sub & 1;

        // exp + bf16 convert + smem store (transposed is NOT needed: row-major, k fast)
        __nv_bfloat16* adst = &sA[buf][lrow * LDSR + khalf * 16];
        __nv_bfloat16* bdst = &sB[buf][lrow * LDSR + khalf * 16];
#pragma unroll
        for (int j = 0; j < 4; j++) {
            float ax = __expf(rx[j].x), ay = __expf(rx[j].y);
            float az = __expf(rx[j].z), aw = __expf(rx[j].w);
            ((__nv_bfloat162*)(adst + j * 4))[0] = __floats2bfloat162_rn(ax, ay);
            ((__nv_bfloat162*)(adst + j * 4))[1] = __floats2bfloat162_rn(az, aw);
            float bx = __expf(rw[j].x), by = __expf(rw[j].y);
            float bz = __expf(rw[j].z), bw = __expf(rw[j].w);
            rsum += (bx + by) + (bz + bw);
            ((__nv_bfloat162*)(bdst + j * 4))[0] = __floats2bfloat162_rn(bx, by);
            ((__nv_bfloat162*)(bdst + j * 4))[1] = __floats2bfloat162_rn(bz, bw);
        }

        // prefetch next stage (overlaps with barrier + MMA)
        if (sub + 1 < NSUB) {
#pragma unroll
            for (int j = 0; j < 4; j++) {
                rx[j] = xp4[(sub + 1) * 8 + khalf * 4 + j];
                rw[j] = wp4[(sub + 1) * 8 + khalf * 4 + j];
            }
        }

        __syncthreads();   // one barrier per stage: covers WAR on buf via 2-deep buffering

        // MMA over this 32-wide K slab (2 x k16 steps)
#pragma unroll
        for (int ks = 0; ks < KSUB; ks += 16) {
            uint32_t af[4][4];
#pragma unroll
            for (int mi = 0; mi < 4; mi++) {
                int ar = m0 + mi * 16 + (lane & 15);
                int ac = ks + (lane >> 4) * 8;
                uint32_t addr = smem_u32(&sA[buf][ar * LDSR + ac]);
                asm volatile(
                    "ldmatrix.sync.aligned.m8n8.x4.shared.b16 {%0,%1,%2,%3}, [%4];"
                    : "=r"(af[mi][0]), "=r"(af[mi][1]), "=r"(af[mi][2]), "=r"(af[mi][3])
                    : "r"(addr));
            }
            uint32_t bf[2][4];
#pragma unroll
            for (int nb = 0; nb < 2; nb++) {
                int g = lane >> 3, r = lane & 7;
                int br = n0 + nb * 16 + (g >> 1) * 8 + r;
                int bc = ks + (g & 1) * 8;
                uint32_t addr = smem_u32(&sB[buf][br * LDSR + bc]);
                asm volatile(
                    "ldmatrix.sync.aligned.m8n8.x4.shared.b16 {%0,%1,%2,%3}, [%4];"
                    : "=r"(bf[nb][0]), "=r"(bf[nb][1]), "=r"(bf[nb][2]), "=r"(bf[nb][3])
                    : "r"(addr));
            }
#pragma unroll
            for (int mi = 0; mi < 4; mi++)
#pragma unroll
                for (int nj = 0; nj < 4; nj++) {
                    uint32_t b0 = bf[nj >> 1][(nj & 1) * 2 + 0];
                    uint32_t b1 = bf[nj >> 1][(nj & 1) * 2 + 1];
                    asm volatile(
                        "mma.sync.aligned.m16n8k16.row.col.f32.bf16.bf16.f32 "
                        "{%0,%1,%2,%3}, {%4,%5,%6,%7}, {%8,%9}, {%0,%1,%2,%3};"
                        : "+f"(acc[mi][nj][0]), "+f"(acc[mi][nj][1]),
                          "+f"(acc[mi][nj][2]), "+f"(acc[mi][nj][3])
                        : "r"(af[mi][0]), "r"(af[mi][1]), "r"(af[mi][2]), "r"(af[mi][3]),
                          "r"(b0), "r"(b1));
                }
        }
    }

    // row-sum partials: each row covered by thread pair (tid, tid^1)
    rsum += __shfl_xor_sync(0xffffffffu, rsum, 1);
    if (khalf == 0) g_rpart[blockIdx.x * O_DIM + lrow] = rsum;

    // store 128x128 f32 partial tile
    float* dst = g_part + (size_t)blockIdx.x * (B_DIM * O_DIM);
#pragma unroll
    for (int mi = 0; mi < 4; mi++)
#pragma unroll
        for (int nj = 0; nj < 4; nj++) {
            int gr = m0 + mi * 16 + (lane >> 2);
            int gc = n0 + nj * 8 + (lane & 3) * 2;
            *(float2*)&dst[gr * O_DIM + gc] =
                make_float2(acc[mi][nj][0], acc[mi][nj][1]);
            *(float2*)&dst[(gr + 8) * O_DIM + gc] =
                make_float2(acc[mi][nj][2], acc[mi][nj][3]);
        }
}

// 8 threads cooperate per output: serial load chain 128 -> 16.
__global__ __launch_bounds__(1024)
void srl_finalize_kernel(float* __restrict__ out) {
    const int b  = blockIdx.x;
    const int t  = threadIdx.x;
    const int o  = t & 127;
    const int sg = t >> 7;        // 0..7
    float s = 0.f, r = 0.f;
#pragma unroll
    for (int i = 0; i < 16; i++) {
        int sp = sg * 16 + i;
        s += g_part[(size_t)sp * (B_DIM * O_DIM) + b * O_DIM + o];
        r += g_rpart[sp * O_DIM + o];
    }
    __shared__ float ss[8][128];
    __shared__ float sr[8][128];
    ss[sg][o] = s;
    sr[sg][o] = r;
    __syncthreads();
    if (sg == 0) {
        float S = 0.f, R = 0.f;
#pragma unroll
        for (int i = 0; i < 8; i++) { S += ss[i][o]; R += sr[i][o]; }
        out[b * O_DIM + o] = __logf(S) - __logf(R);
    }
}

extern "C" void kernel_launch(void* const* d_in, const int* in_sizes, int n_in,
                              void* d_out, int out_size) {
    (void)in_sizes; (void)n_in; (void)out_size;
    const float* x = (const float*)d_in[0];   // [128, 16384]
    const float* w = (const float*)d_in[1];   // [128, 16384]
    float* out = (float*)d_out;               // [128, 128]

    srl_gemm_kernel<<<NSPLIT, 256>>>(x, w);
    srl_finalize_kernel<<<B_DIM, 1024>>>(out);
}

// round 4
// speedup vs baseline: 2.3103x; 1.1487x over previous
#include <cuda_runtime.h>
#include <cuda_bf16.h>
#include <cuda_fp16.h>
#include <cstdint>

// ============================================================================
// out[b,o] = log( sum_k e^x[b,k] * e^w[o,k] ) - log( sum_k e^w[o,k] )
// Linear domain, split-K bf16 tensor-core GEMM, fp16 split-K partials.
// ============================================================================

#define B_DIM  128
#define O_DIM  128
#define K_DIM  16384
#define NSPLIT 128
#define KCHUNK 128
#define NSUB   4
#define KSUB   32
#define LDSR   40     // smem row stride (bf16 elems): 80B, conflict-free ldmatrix

__device__ __half2 g_part[NSPLIT * B_DIM * (O_DIM / 2)];  // [sp][b][o/2] 4MB
__device__ float   g_rpart[NSPLIT * O_DIM];               // [sp][o]

__device__ __forceinline__ uint32_t smem_u32(const void* p) {
    return (uint32_t)__cvta_generic_to_shared(p);
}

__device__ __forceinline__ uint32_t bf2_bits(__nv_bfloat162 v) {
    union { __nv_bfloat162 h; uint32_t u; } cvt;
    cvt.h = v;
    return cvt.u;
}

__global__ __launch_bounds__(512, 1)
void srl_gemm_kernel(const float* __restrict__ x, const float* __restrict__ w) {
    __shared__ __align__(16) __nv_bfloat16 sA[2][B_DIM * LDSR];
    __shared__ __align__(16) __nv_bfloat16 sB[2][B_DIM * LDSR];

    const int tid  = threadIdx.x;
    const int lane = tid & 31;
    const int wid  = tid >> 5;
    const int kbase = blockIdx.x * KCHUNK;

    // Loader mapping: 4 threads per row, each owns 8 contiguous k (32B) per stage.
    const int lrow = tid >> 2;
    const int kq   = tid & 3;
    const float4* xp4 = (const float4*)(x + (size_t)lrow * K_DIM + kbase + kq * 8);
    const float4* wp4 = (const float4*)(w + (size_t)lrow * K_DIM + kbase + kq * 8);

    // 16 warps: 4x4 grid of 32x32 output tiles.
    const int m0 = (wid >> 2) * 32;
    const int n0 = (wid & 3) * 32;

    float acc[2][4][4];
#pragma unroll
    for (int mi = 0; mi < 2; mi++)
#pragma unroll
        for (int nj = 0; nj < 4; nj++)
#pragma unroll
            for (int q = 0; q < 4; q++) acc[mi][nj][q] = 0.f;

    float4 rx[2], rw[2];
#pragma unroll
    for (int j = 0; j < 2; j++) { rx[j] = xp4[j]; rw[j] = wp4[j]; }

    float rsum = 0.f;

    for (int sub = 0; sub < NSUB; ++sub) {
        const int buf = sub & 1;

        // exp + bf16 + smem (8B stores)
        uint2* adst = (uint2*)&sA[buf][lrow * LDSR + kq * 8];
        uint2* bdst = (uint2*)&sB[buf][lrow * LDSR + kq * 8];
#pragma unroll
        for (int j = 0; j < 2; j++) {
            float ax = __expf(rx[j].x), ay = __expf(rx[j].y);
            float az = __expf(rx[j].z), aw = __expf(rx[j].w);
            uint2 av;
            av.x = bf2_bits(__floats2bfloat162_rn(ax, ay));
            av.y = bf2_bits(__floats2bfloat162_rn(az, aw));
            adst[j] = av;
            float bx = __expf(rw[j].x), by = __expf(rw[j].y);
            float bz = __expf(rw[j].z), bw = __expf(rw[j].w);
            rsum += (bx + by) + (bz + bw);
            uint2 bv;
            bv.x = bf2_bits(__floats2bfloat162_rn(bx, by));
            bv.y = bf2_bits(__floats2bfloat162_rn(bz, bw));
            bdst[j] = bv;
        }

        if (sub + 1 < NSUB) {
#pragma unroll
            for (int j = 0; j < 2; j++) {
                rx[j] = xp4[(sub + 1) * 8 + j];
                rw[j] = wp4[(sub + 1) * 8 + j];
            }
        }

        __syncthreads();   // safe: buffer re-written 2 stages after its last read

#pragma unroll
        for (int ks = 0; ks < KSUB; ks += 16) {
            uint32_t af[2][4];
#pragma unroll
            for (int mi = 0; mi < 2; mi++) {
                int ar = m0 + mi * 16 + (lane & 15);
                int ac = ks + (lane >> 4) * 8;
                uint32_t addr = smem_u32(&sA[buf][ar * LDSR + ac]);
                asm volatile(
                    "ldmatrix.sync.aligned.m8n8.x4.shared.b16 {%0,%1,%2,%3}, [%4];"
                    : "=r"(af[mi][0]), "=r"(af[mi][1]), "=r"(af[mi][2]), "=r"(af[mi][3])
                    : "r"(addr));
            }
            uint32_t bfr[2][4];
#pragma unroll
            for (int nb = 0; nb < 2; nb++) {
                int g = lane >> 3, r = lane & 7;
                int br = n0 + nb * 16 + (g >> 1) * 8 + r;
                int bc = ks + (g & 1) * 8;
                uint32_t addr = smem_u32(&sB[buf][br * LDSR + bc]);
                asm volatile(
                    "ldmatrix.sync.aligned.m8n8.x4.shared.b16 {%0,%1,%2,%3}, [%4];"
                    : "=r"(bfr[nb][0]), "=r"(bfr[nb][1]), "=r"(bfr[nb][2]), "=r"(bfr[nb][3])
                    : "r"(addr));
            }
#pragma unroll
            for (int mi = 0; mi < 2; mi++)
#pragma unroll
                for (int nj = 0; nj < 4; nj++) {
                    uint32_t b0 = bfr[nj >> 1][(nj & 1) * 2 + 0];
                    uint32_t b1 = bfr[nj >> 1][(nj & 1) * 2 + 1];
                    asm volatile(
                        "mma.sync.aligned.m16n8k16.row.col.f32.bf16.bf16.f32 "
                        "{%0,%1,%2,%3}, {%4,%5,%6,%7}, {%8,%9}, {%0,%1,%2,%3};"
                        : "+f"(acc[mi][nj][0]), "+f"(acc[mi][nj][1]),
                          "+f"(acc[mi][nj][2]), "+f"(acc[mi][nj][3])
                        : "r"(af[mi][0]), "r"(af[mi][1]), "r"(af[mi][2]), "r"(af[mi][3]),
                          "r"(b0), "r"(b1));
                }
        }
    }

    // rsum: 4 threads per row -> reduce pairs within warp (same-row lanes adjacent)
    rsum += __shfl_xor_sync(0xffffffffu, rsum, 1);
    rsum += __shfl_xor_sync(0xffffffffu, rsum, 2);
    if (kq == 0) g_rpart[blockIdx.x * O_DIM + lrow] = rsum;

    // store fp16 partial tile [sp][b][o/2]
    __half2* dst = g_part + (size_t)blockIdx.x * (B_DIM * (O_DIM / 2));
#pragma unroll
    for (int mi = 0; mi < 2; mi++)
#pragma unroll
        for (int nj = 0; nj < 4; nj++) {
            int gr = m0 + mi * 16 + (lane >> 2);
            int gc = n0 + nj * 8 + (lane & 3) * 2;
            dst[gr * (O_DIM / 2) + (gc >> 1)] =
                __floats2half2_rn(acc[mi][nj][0], acc[mi][nj][1]);
            dst[(gr + 8) * (O_DIM / 2) + (gc >> 1)] =
                __floats2half2_rn(acc[mi][nj][2], acc[mi][nj][3]);
        }
}

// Finalize: per b, 16 sp-groups x 8 coalesced half2 loads, smem reduce, log.
__global__ __launch_bounds__(1024)
void srl_finalize_kernel(float* __restrict__ out) {
    const int b  = blockIdx.x;
    const int t  = threadIdx.x;
    const int o2 = t & 63;        // half2 index -> outputs (2*o2, 2*o2+1)
    const int sg = t >> 6;        // 0..15

    float s0 = 0.f, s1 = 0.f, r0 = 0.f, r1 = 0.f;
#pragma unroll
    for (int i = 0; i < 8; i++) {
        int sp = sg * 8 + i;
        float2 sv = __half22float2(g_part[(size_t)sp * (B_DIM * 64) + b * 64 + o2]);
        s0 += sv.x; s1 += sv.y;
        float2 rv = *(const float2*)&g_rpart[sp * O_DIM + 2 * o2];
        r0 += rv.x; r1 += rv.y;
    }

    __shared__ float4 red[16][64];
    red[sg][o2] = make_float4(s0, s1, r0, r1);
    __syncthreads();

    if (t < 64) {
        float S0 = 0.f, S1 = 0.f, R0 = 0.f, R1 = 0.f;
#pragma unroll
        for (int i = 0; i < 16; i++) {
            float4 v = red[i][t];
            S0 += v.x; S1 += v.y; R0 += v.z; R1 += v.w;
        }
        *(float2*)&out[b * O_DIM + 2 * t] =
            make_float2(__logf(S0) - __logf(R0), __logf(S1) - __logf(R1));
    }
}

extern "C" void kernel_launch(void* const* d_in, const int* in_sizes, int n_in,
                              void* d_out, int out_size) {
    (void)in_sizes; (void)n_in; (void)out_size;
    const float* x = (const float*)d_in[0];   // [128, 16384]
    const float* w = (const float*)d_in[1];   // [128, 16384]
    float* out = (float*)d_out;               // [128, 128]

    srl_gemm_kernel<<<NSPLIT, 512>>>(x, w);
    srl_finalize_kernel<<<B_DIM, 1024>>>(out);
}